// round 1
// baseline (speedup 1.0000x reference)
#include <cuda_runtime.h>
#include <math.h>

// ---------------------------------------------------------------------------
// EoMT transformer layer, fp32 SIMT baseline.
// B=8, SEQ=1124 (1024 patches + 100 queries), EMB=1024, NH=16, HD=64, MLP=4096
// ---------------------------------------------------------------------------

#define BB      8
#define SEQ     1124
#define EMB     1024
#define NH      16
#define HD      64
#define NPATCH  1024
#define NQ      100
#define MLPH    4096
#define NROWS   (BB * SEQ)       /* 8992 */
#define SSTRIDE 1152             /* padded key-dim stride for scores */
#define ATT_SCALE 0.125f         /* 64^-0.5 */

// ---------------- scratch (single __device__ arena; no allocs allowed) ------
static constexpr size_t SZ_XN  = (size_t)NROWS * EMB;        // LN out (reused for LN2)
static constexpr size_t SZ_QKV = (size_t)NROWS * 3 * EMB;
static constexpr size_t SZ_SC  = (size_t)BB * NH * SEQ * SSTRIDE;
static constexpr size_t SZ_ATT = (size_t)NROWS * EMB;
static constexpr size_t SZ_X1  = (size_t)NROWS * EMB;
static constexpr size_t SZ_H1  = (size_t)NROWS * MLPH;

static constexpr size_t OFF_XN  = 0;
static constexpr size_t OFF_QKV = OFF_XN + SZ_XN;
static constexpr size_t OFF_SC  = OFF_QKV + SZ_QKV;
static constexpr size_t OFF_ATT = OFF_SC + SZ_SC;
static constexpr size_t OFF_X1  = OFF_ATT + SZ_ATT;
static constexpr size_t OFF_H1  = OFF_X1 + SZ_X1;
static constexpr size_t SCRATCH_TOTAL = OFF_H1 + SZ_H1;      // ~258M floats ~ 0.96 GB

__device__ float g_scratch[SCRATCH_TOTAL];

// ---------------------------------------------------------------------------
// LayerNorm: one block (256 thr) per row of 1024 floats.
// ---------------------------------------------------------------------------
__global__ void __launch_bounds__(256) ln_kernel(
    const float* __restrict__ in, const float* __restrict__ gam,
    const float* __restrict__ bet, float* __restrict__ out)
{
    int row = blockIdx.x;
    int t = threadIdx.x;
    const float4* inr = (const float4*)(in + (size_t)row * EMB);
    float4 v = inr[t];
    float s  = v.x + v.y + v.z + v.w;
    float s2 = v.x * v.x + v.y * v.y + v.z * v.z + v.w * v.w;

    __shared__ float red[16];
    __shared__ float stats[2];
    #pragma unroll
    for (int o = 16; o > 0; o >>= 1) {
        s  += __shfl_down_sync(0xffffffffu, s,  o);
        s2 += __shfl_down_sync(0xffffffffu, s2, o);
    }
    int warp = t >> 5, lane = t & 31;
    if (lane == 0) { red[warp] = s; red[warp + 8] = s2; }
    __syncthreads();
    if (t == 0) {
        float ts = 0.f, ts2 = 0.f;
        #pragma unroll
        for (int w = 0; w < 8; w++) { ts += red[w]; ts2 += red[w + 8]; }
        float mean = ts * (1.0f / EMB);
        float var  = ts2 * (1.0f / EMB) - mean * mean;
        stats[0] = mean;
        stats[1] = rsqrtf(var + 1e-6f);
    }
    __syncthreads();
    float mean = stats[0], inv = stats[1];
    float4 gg = ((const float4*)gam)[t];
    float4 bb = ((const float4*)bet)[t];
    float4 o;
    o.x = (v.x - mean) * inv * gg.x + bb.x;
    o.y = (v.y - mean) * inv * gg.y + bb.y;
    o.z = (v.z - mean) * inv * gg.z + bb.z;
    o.w = (v.w - mean) * inv * gg.w + bb.w;
    ((float4*)(out + (size_t)row * EMB))[t] = o;
}

// ---------------------------------------------------------------------------
// Generic SGEMM: C[MxN] = A[MxK] @ B[KxN], all row-major. 128x128x8 tiles,
// 256 threads, 8x8 per thread. N % 128 == 0, K % 8 == 0 (always true here).
// EPI: 0 = plain store, 1 = +bias, 2 = +bias+residual, 3 = gelu(+bias)
// ---------------------------------------------------------------------------
__device__ __forceinline__ float gelu_f(float v)
{
    return 0.5f * v * (1.0f + erff(v * 0.70710678118654752440f));
}

template <int EPI>
__global__ void __launch_bounds__(256) sgemm_kernel(
    const float* __restrict__ A, const float* __restrict__ Bm,
    float* __restrict__ C, int M, int N, int K,
    const float* __restrict__ bias, const float* __restrict__ res)
{
    __shared__ float As[8][128];
    __shared__ float Bs[8][128];
    int t  = threadIdx.x;
    int m0 = blockIdx.y * 128, n0 = blockIdx.x * 128;
    int a_m = t >> 1, a_k = (t & 1) << 2;
    int b_k = t >> 5, b_n = (t & 31) << 2;
    int ty = t >> 4, tx = t & 15;

    bool a_ok = (m0 + a_m) < M;
    const float* Ap = A + (size_t)(m0 + a_m) * K + a_k;
    const float* Bp = Bm + (size_t)b_k * N + n0 + b_n;

    float acc[8][8];
    #pragma unroll
    for (int i = 0; i < 8; i++)
        #pragma unroll
        for (int j = 0; j < 8; j++) acc[i][j] = 0.f;

    for (int k0 = 0; k0 < K; k0 += 8) {
        float4 av = a_ok ? *(const float4*)(Ap + k0) : make_float4(0, 0, 0, 0);
        float4 bv = *(const float4*)(Bp + (size_t)k0 * N);
        __syncthreads();
        As[a_k + 0][a_m] = av.x; As[a_k + 1][a_m] = av.y;
        As[a_k + 2][a_m] = av.z; As[a_k + 3][a_m] = av.w;
        *(float4*)&Bs[b_k][b_n] = bv;
        __syncthreads();
        #pragma unroll
        for (int kk = 0; kk < 8; kk++) {
            float4 a0 = *(const float4*)&As[kk][ty * 8];
            float4 a1 = *(const float4*)&As[kk][ty * 8 + 4];
            float4 b0 = *(const float4*)&Bs[kk][tx * 8];
            float4 b1 = *(const float4*)&Bs[kk][tx * 8 + 4];
            float aa[8] = {a0.x, a0.y, a0.z, a0.w, a1.x, a1.y, a1.z, a1.w};
            float bb[8] = {b0.x, b0.y, b0.z, b0.w, b1.x, b1.y, b1.z, b1.w};
            #pragma unroll
            for (int i = 0; i < 8; i++)
                #pragma unroll
                for (int j = 0; j < 8; j++)
                    acc[i][j] = fmaf(aa[i], bb[j], acc[i][j]);
        }
    }

    #pragma unroll
    for (int i = 0; i < 8; i++) {
        int m = m0 + ty * 8 + i;
        if (m < M) {
            size_t base = (size_t)m * N + n0 + tx * 8;
            #pragma unroll
            for (int jv = 0; jv < 2; jv++) {
                float4 o;
                o.x = acc[i][jv * 4 + 0]; o.y = acc[i][jv * 4 + 1];
                o.z = acc[i][jv * 4 + 2]; o.w = acc[i][jv * 4 + 3];
                if (EPI >= 1) {
                    float4 bb = *(const float4*)&bias[n0 + tx * 8 + jv * 4];
                    o.x += bb.x; o.y += bb.y; o.z += bb.z; o.w += bb.w;
                }
                if (EPI == 2) {
                    float4 r = *(const float4*)&res[base + jv * 4];
                    o.x += r.x; o.y += r.y; o.z += r.z; o.w += r.w;
                }
                if (EPI == 3) {
                    o.x = gelu_f(o.x); o.y = gelu_f(o.y);
                    o.z = gelu_f(o.z); o.w = gelu_f(o.w);
                }
                *(float4*)&C[base + jv * 4] = o;
            }
        }
    }
}

// ---------------------------------------------------------------------------
// Attention scores: S[bh, i, j] = SCALE * sum_d Q[b,i,h,d] * K[b,j,h,d]
// 64x64 output tile per block, full K-dim (64) staged in smem.
// grid: (x = 18 key tiles, y = 18 query tiles, z = 128 bh)
// ---------------------------------------------------------------------------
__global__ void __launch_bounds__(256) score_kernel(
    const float* __restrict__ qkv, float* __restrict__ S)
{
    __shared__ float Qs[64][68];   // [d][m], padded for 16B-aligned float4 rows
    __shared__ float Ks[64][68];   // [d][n]
    int bh = blockIdx.z;
    int b = bh >> 4, h = bh & 15;
    const float* Qp = qkv + (size_t)b * SEQ * (3 * EMB) + h * HD;
    const float* Kp = Qp + EMB;
    float* Sp = S + (size_t)bh * SEQ * SSTRIDE;
    int i0 = blockIdx.y * 64, j0 = blockIdx.x * 64;
    int t = threadIdx.x;
    int lr = t >> 4, lc = (t & 15) << 2;

    #pragma unroll
    for (int p = 0; p < 4; p++) {
        int m = p * 16 + lr;
        float4 q4 = (i0 + m < SEQ)
            ? *(const float4*)(Qp + (size_t)(i0 + m) * (3 * EMB) + lc)
            : make_float4(0, 0, 0, 0);
        float4 k4 = (j0 + m < SEQ)
            ? *(const float4*)(Kp + (size_t)(j0 + m) * (3 * EMB) + lc)
            : make_float4(0, 0, 0, 0);
        Qs[lc + 0][m] = q4.x; Qs[lc + 1][m] = q4.y;
        Qs[lc + 2][m] = q4.z; Qs[lc + 3][m] = q4.w;
        Ks[lc + 0][m] = k4.x; Ks[lc + 1][m] = k4.y;
        Ks[lc + 2][m] = k4.z; Ks[lc + 3][m] = k4.w;
    }
    __syncthreads();

    int ty = t >> 4, tx = t & 15;
    float acc[4][4] = {};
    #pragma unroll 8
    for (int d = 0; d < 64; d++) {
        float4 a  = *(const float4*)&Qs[d][ty * 4];
        float4 bv = *(const float4*)&Ks[d][tx * 4];
        acc[0][0] = fmaf(a.x, bv.x, acc[0][0]); acc[0][1] = fmaf(a.x, bv.y, acc[0][1]);
        acc[0][2] = fmaf(a.x, bv.z, acc[0][2]); acc[0][3] = fmaf(a.x, bv.w, acc[0][3]);
        acc[1][0] = fmaf(a.y, bv.x, acc[1][0]); acc[1][1] = fmaf(a.y, bv.y, acc[1][1]);
        acc[1][2] = fmaf(a.y, bv.z, acc[1][2]); acc[1][3] = fmaf(a.y, bv.w, acc[1][3]);
        acc[2][0] = fmaf(a.z, bv.x, acc[2][0]); acc[2][1] = fmaf(a.z, bv.y, acc[2][1]);
        acc[2][2] = fmaf(a.z, bv.z, acc[2][2]); acc[2][3] = fmaf(a.z, bv.w, acc[2][3]);
        acc[3][0] = fmaf(a.w, bv.x, acc[3][0]); acc[3][1] = fmaf(a.w, bv.y, acc[3][1]);
        acc[3][2] = fmaf(a.w, bv.z, acc[3][2]); acc[3][3] = fmaf(a.w, bv.w, acc[3][3]);
    }

    #pragma unroll
    for (int i = 0; i < 4; i++) {
        int ii = i0 + ty * 4 + i;
        int jj = j0 + tx * 4;
        if (ii < SEQ && jj < SEQ) {
            float4 o;
            o.x = acc[i][0] * ATT_SCALE; o.y = acc[i][1] * ATT_SCALE;
            o.z = acc[i][2] * ATT_SCALE; o.w = acc[i][3] * ATT_SCALE;
            *(float4*)&Sp[(size_t)ii * SSTRIDE + jj] = o;
        }
    }
}

// ---------------------------------------------------------------------------
// Masked softmax over key dim. One block (128 thr) per (row, bh).
// Rows >= NPATCH are query rows: keys < NPATCH masked by mask[b, qi, key].
// ---------------------------------------------------------------------------
__global__ void __launch_bounds__(128) softmax_kernel(
    float* __restrict__ S, const float* __restrict__ mask)
{
    int row = blockIdx.x;
    int bh  = blockIdx.y;
    int b = bh >> 4;
    float* Sp = S + ((size_t)bh * SEQ + row) * SSTRIDE;
    const float* mrow = (row >= NPATCH)
        ? mask + ((size_t)b * NQ + (row - NPATCH)) * NPATCH : nullptr;
    int t = threadIdx.x;

    float v[9];
    float mx = -3.0e38f;
    #pragma unroll
    for (int i = 0; i < 9; i++) {
        int j = t + i * 128;
        float val = -3.0e38f;
        if (j < SEQ) {
            val = Sp[j];
            if (mrow && j < NPATCH && !(mrow[j] > 0.5f)) val = -1.0e9f;
        }
        v[i] = val;
        mx = fmaxf(mx, val);
    }

    __shared__ float redm[4];
    __shared__ float reds[4];
    #pragma unroll
    for (int o = 16; o > 0; o >>= 1)
        mx = fmaxf(mx, __shfl_xor_sync(0xffffffffu, mx, o));
    if ((t & 31) == 0) redm[t >> 5] = mx;
    __syncthreads();
    mx = fmaxf(fmaxf(redm[0], redm[1]), fmaxf(redm[2], redm[3]));

    float sum = 0.f;
    #pragma unroll
    for (int i = 0; i < 9; i++) {
        float e = __expf(v[i] - mx);   // -3e38 / -1e9 entries underflow to 0
        v[i] = e;
        sum += e;
    }
    #pragma unroll
    for (int o = 16; o > 0; o >>= 1)
        sum += __shfl_xor_sync(0xffffffffu, sum, o);
    if ((t & 31) == 0) reds[t >> 5] = sum;
    __syncthreads();
    sum = reds[0] + reds[1] + reds[2] + reds[3];
    float inv = __fdividef(1.0f, sum);

    #pragma unroll
    for (int i = 0; i < 9; i++) {
        int j = t + i * 128;
        if (j < SEQ) Sp[j] = v[i] * inv;
    }
}

// ---------------------------------------------------------------------------
// AV: out[b, i, h*64+d] = sum_j attn[bh, i, j] * V[b, j, h, d]
// 64 (rows) x 64 (full head dim) tile per block, K chunks of 32.
// grid: (x = 18 row tiles, y = 128 bh)
// ---------------------------------------------------------------------------
__global__ void __launch_bounds__(256) av_kernel(
    const float* __restrict__ qkv, const float* __restrict__ attn,
    float* __restrict__ outp)
{
    __shared__ float As[32][68];   // [k][m]
    __shared__ float Bs[32][64];   // [k][d]
    int bh = blockIdx.y;
    int b = bh >> 4, h = bh & 15;
    const float* Vp = qkv + (size_t)b * SEQ * (3 * EMB) + 2 * EMB + h * HD;
    const float* Ap = attn + (size_t)bh * SEQ * SSTRIDE;
    int i0 = blockIdx.x * 64;
    int t = threadIdx.x;
    int ty = t >> 4, tx = t & 15;

    float acc[4][4] = {};
    for (int j0 = 0; j0 < SEQ; j0 += 32) {
        __syncthreads();
        #pragma unroll
        for (int p = 0; p < 2; p++) {
            int idx = p * 256 + t;
            int am = idx >> 3, k = (idx & 7) << 2;
            float4 a4 = (i0 + am < SEQ && j0 + k < SEQ)
                ? *(const float4*)(Ap + (size_t)(i0 + am) * SSTRIDE + j0 + k)
                : make_float4(0, 0, 0, 0);
            As[k + 0][am] = a4.x; As[k + 1][am] = a4.y;
            As[k + 2][am] = a4.z; As[k + 3][am] = a4.w;
            int br = idx >> 4, d = (idx & 15) << 2;
            float4 b4 = (j0 + br < SEQ)
                ? *(const float4*)(Vp + (size_t)(j0 + br) * (3 * EMB) + d)
                : make_float4(0, 0, 0, 0);
            *(float4*)&Bs[br][d] = b4;
        }
        __syncthreads();
        #pragma unroll
        for (int k = 0; k < 32; k++) {
            float4 a  = *(const float4*)&As[k][ty * 4];
            float4 bv = *(const float4*)&Bs[k][tx * 4];
            acc[0][0] = fmaf(a.x, bv.x, acc[0][0]); acc[0][1] = fmaf(a.x, bv.y, acc[0][1]);
            acc[0][2] = fmaf(a.x, bv.z, acc[0][2]); acc[0][3] = fmaf(a.x, bv.w, acc[0][3]);
            acc[1][0] = fmaf(a.y, bv.x, acc[1][0]); acc[1][1] = fmaf(a.y, bv.y, acc[1][1]);
            acc[1][2] = fmaf(a.y, bv.z, acc[1][2]); acc[1][3] = fmaf(a.y, bv.w, acc[1][3]);
            acc[2][0] = fmaf(a.z, bv.x, acc[2][0]); acc[2][1] = fmaf(a.z, bv.y, acc[2][1]);
            acc[2][2] = fmaf(a.z, bv.z, acc[2][2]); acc[2][3] = fmaf(a.z, bv.w, acc[2][3]);
            acc[3][0] = fmaf(a.w, bv.x, acc[3][0]); acc[3][1] = fmaf(a.w, bv.y, acc[3][1]);
            acc[3][2] = fmaf(a.w, bv.z, acc[3][2]); acc[3][3] = fmaf(a.w, bv.w, acc[3][3]);
        }
    }

    #pragma unroll
    for (int i = 0; i < 4; i++) {
        int ii = i0 + ty * 4 + i;
        if (ii < SEQ) {
            float4 o;
            o.x = acc[i][0]; o.y = acc[i][1]; o.z = acc[i][2]; o.w = acc[i][3];
            *(float4*)&outp[((size_t)b * SEQ + ii) * EMB + h * HD + tx * 4] = o;
        }
    }
}

// ---------------------------------------------------------------------------
extern "C" void kernel_launch(void* const* d_in, const int* in_sizes, int n_in,
                              void* d_out, int out_size)
{
    (void)in_sizes; (void)n_in; (void)out_size;
    const float* x      = (const float*)d_in[0];
    const float* mask   = (const float*)d_in[1];
    const float* qkv_w  = (const float*)d_in[2];
    const float* proj_w = (const float*)d_in[3];
    const float* proj_b = (const float*)d_in[4];
    const float* ln1_g  = (const float*)d_in[5];
    const float* ln1_b  = (const float*)d_in[6];
    const float* ln2_g  = (const float*)d_in[7];
    const float* ln2_b  = (const float*)d_in[8];
    const float* fc1_w  = (const float*)d_in[9];
    const float* fc1_b  = (const float*)d_in[10];
    const float* fc2_w  = (const float*)d_in[11];
    const float* fc2_b  = (const float*)d_in[12];
    float* out = (float*)d_out;

    float* scratch = nullptr;
    cudaGetSymbolAddress((void**)&scratch, g_scratch);
    float* xn   = scratch + OFF_XN;
    float* qkv  = scratch + OFF_QKV;
    float* sc   = scratch + OFF_SC;
    float* att  = scratch + OFF_ATT;
    float* x1   = scratch + OFF_X1;
    float* h1   = scratch + OFF_H1;

    const int MT = (NROWS + 127) / 128;  // 71

    // 1. LN1
    ln_kernel<<<NROWS, 256>>>(x, ln1_g, ln1_b, xn);
    // 2. QKV = xn @ qkv_w            [8992 x 3072]
    sgemm_kernel<0><<<dim3(3 * EMB / 128, MT), 256>>>(
        xn, qkv_w, qkv, NROWS, 3 * EMB, EMB, nullptr, nullptr);
    // 3. scores = Q K^T * scale
    score_kernel<<<dim3(18, 18, BB * NH), 256>>>(qkv, sc);
    // 4. masked softmax
    softmax_kernel<<<dim3(SEQ, BB * NH), 128>>>(sc, mask);
    // 5. att = attn @ V
    av_kernel<<<dim3(18, BB * NH), 256>>>(qkv, sc, att);
    // 6. x1 = x + att @ proj_w + proj_b
    sgemm_kernel<2><<<dim3(EMB / 128, MT), 256>>>(
        att, proj_w, x1, NROWS, EMB, EMB, proj_b, x);
    // 7. LN2 (reuse xn)
    ln_kernel<<<NROWS, 256>>>(x1, ln2_g, ln2_b, xn);
    // 8. h1 = gelu(xn @ fc1_w + fc1_b)   [8992 x 4096]
    sgemm_kernel<3><<<dim3(MLPH / 128, MT), 256>>>(
        xn, fc1_w, h1, NROWS, MLPH, EMB, fc1_b, nullptr);
    // 9. out = x1 + h1 @ fc2_w + fc2_b
    sgemm_kernel<2><<<dim3(EMB / 128, MT), 256>>>(
        h1, fc2_w, out, NROWS, EMB, MLPH, fc2_b, x1);
}

// round 6
// speedup vs baseline: 3.0109x; 3.0109x over previous
#include <cuda_runtime.h>
#include <math.h>
#include <stdint.h>

// ---------------------------------------------------------------------------
// EoMT transformer layer — tf32 mma.sync tensor-core version.
// B=8, SEQ=1124 (1024 patches + 100 queries), EMB=1024, NH=16, HD=64, MLP=4096
// ---------------------------------------------------------------------------

#define BB      8
#define SEQ     1124
#define EMB     1024
#define NH      16
#define HD      64
#define NPATCH  1024
#define NQ      100
#define MLPH    4096
#define NROWS   (BB * SEQ)       /* 8992 */
#define SPAD    1152             /* padded seq (9*128) for score scratch */
#define ATT_SCALE 0.125f

// ---------------- scratch arena ---------------------------------------------
static constexpr size_t SZ_XN  = (size_t)NROWS * EMB;
static constexpr size_t SZ_QKV = (size_t)NROWS * 3 * EMB;
static constexpr size_t SZ_SC  = (size_t)BB * NH * SPAD * SPAD;
static constexpr size_t SZ_ATT = (size_t)NROWS * EMB;
static constexpr size_t SZ_X1  = (size_t)NROWS * EMB;
static constexpr size_t SZ_H1  = (size_t)NROWS * MLPH;

static constexpr size_t OFF_XN  = 0;
static constexpr size_t OFF_QKV = OFF_XN + SZ_XN;
static constexpr size_t OFF_SC  = OFF_QKV + SZ_QKV;
static constexpr size_t OFF_ATT = OFF_SC + SZ_SC;
static constexpr size_t OFF_X1  = OFF_ATT + SZ_ATT;
static constexpr size_t OFF_H1  = OFF_X1 + SZ_X1;
static constexpr size_t SCRATCH_TOTAL = OFF_H1 + SZ_H1;   // ~1.05 GB

__device__ float g_scratch[SCRATCH_TOTAL];

// ---------------------------------------------------------------------------
__device__ __forceinline__ uint32_t f2t(float f)
{
    uint32_t u;
    asm("cvt.rna.tf32.f32 %0, %1;" : "=r"(u) : "f"(f));
    return u;
}

__device__ __forceinline__ void mma_tf32(float* c, uint32_t a0, uint32_t a1,
                                         uint32_t a2, uint32_t a3,
                                         uint32_t b0, uint32_t b1)
{
    asm volatile(
        "mma.sync.aligned.m16n8k8.row.col.f32.tf32.tf32.f32 "
        "{%0,%1,%2,%3}, {%4,%5,%6,%7}, {%8,%9}, {%0,%1,%2,%3};"
        : "+f"(c[0]), "+f"(c[1]), "+f"(c[2]), "+f"(c[3])
        : "r"(a0), "r"(a1), "r"(a2), "r"(a3), "r"(b0), "r"(b1));
}

__device__ __forceinline__ float gelu_f(float v)
{
    return 0.5f * v * (1.0f + erff(v * 0.70710678118654752440f));
}

__device__ __forceinline__ float4 f4zero() { return make_float4(0.f, 0.f, 0.f, 0.f); }

// ---------------------------------------------------------------------------
// LayerNorm: one block (256 thr) per row of 1024 floats.
// ---------------------------------------------------------------------------
__global__ void __launch_bounds__(256) ln_kernel(
    const float* __restrict__ in, const float* __restrict__ gam,
    const float* __restrict__ bet, float* __restrict__ out)
{
    int row = blockIdx.x;
    int t = threadIdx.x;
    const float4* inr = (const float4*)(in + (size_t)row * EMB);
    float4 v = inr[t];
    float s  = v.x + v.y + v.z + v.w;
    float s2 = v.x * v.x + v.y * v.y + v.z * v.z + v.w * v.w;

    __shared__ float red[16];
    __shared__ float stats[2];
    #pragma unroll
    for (int o = 16; o > 0; o >>= 1) {
        s  += __shfl_down_sync(0xffffffffu, s,  o);
        s2 += __shfl_down_sync(0xffffffffu, s2, o);
    }
    int warp = t >> 5, lane = t & 31;
    if (lane == 0) { red[warp] = s; red[warp + 8] = s2; }
    __syncthreads();
    if (t == 0) {
        float ts = 0.f, ts2 = 0.f;
        #pragma unroll
        for (int w = 0; w < 8; w++) { ts += red[w]; ts2 += red[w + 8]; }
        float mean = ts * (1.0f / EMB);
        float var  = ts2 * (1.0f / EMB) - mean * mean;
        stats[0] = mean;
        stats[1] = rsqrtf(var + 1e-6f);
    }
    __syncthreads();
    float mean = stats[0], inv = stats[1];
    float4 gg = ((const float4*)gam)[t];
    float4 bb = ((const float4*)bet)[t];
    float4 o;
    o.x = (v.x - mean) * inv * gg.x + bb.x;
    o.y = (v.y - mean) * inv * gg.y + bb.y;
    o.z = (v.z - mean) * inv * gg.z + bb.z;
    o.w = (v.w - mean) * inv * gg.w + bb.w;
    ((float4*)(out + (size_t)row * EMB))[t] = o;
}

// ---------------------------------------------------------------------------
// tf32 tensor-core GEMM: C[MxN] = A[MxK] @ B[KxN] (both row-major).
// Block tile 128x128, kTile 32, 8 warps (2x4), warp tile 64x32.
// smem: As[m][k] pad36 (A-frag lane->bank bijective), Bs[k][n] pad136.
// EPI: 0 plain, 1 +bias, 2 +bias+residual, 3 gelu(+bias)
// ---------------------------------------------------------------------------
template <int EPI>
__global__ void __launch_bounds__(256) tgemm_kernel(
    const float* __restrict__ A, const float* __restrict__ Bm,
    float* __restrict__ C, int M, int N, int K,
    const float* __restrict__ bias, const float* __restrict__ res)
{
    __shared__ uint32_t As[128][36];
    __shared__ uint32_t Bs[32][136];
    int t = threadIdx.x;
    int m0 = blockIdx.y * 128, n0 = blockIdx.x * 128;
    int w = t >> 5, lane = t & 31;
    int wm = (w >> 2) * 64, wn = (w & 3) * 32;
    int g = lane >> 2, tg = lane & 3;

    int am = t >> 3, ak = (t & 7) << 2;     // A: 32 rows/pass x 8 float4, 4 passes
    int bk = t >> 5, bn = (t & 31) << 2;    // B: 8 rows/pass x 32 float4, 4 passes

    float4 aR[4], bR[4];
    #pragma unroll
    for (int p = 0; p < 4; p++) {
        int r = m0 + am + p * 32;
        aR[p] = (r < M) ? *(const float4*)(A + (size_t)r * K + ak) : f4zero();
        bR[p] = *(const float4*)(Bm + (size_t)(bk + p * 8) * N + n0 + bn);
    }

    float acc[4][4][4];
    #pragma unroll
    for (int i = 0; i < 4; i++)
        #pragma unroll
        for (int j = 0; j < 4; j++)
            #pragma unroll
            for (int q = 0; q < 4; q++) acc[i][j][q] = 0.f;

    for (int k0 = 0; k0 < K; k0 += 32) {
        __syncthreads();
        #pragma unroll
        for (int p = 0; p < 4; p++) {
            uint32_t* ar = &As[am + p * 32][ak];
            ar[0] = f2t(aR[p].x); ar[1] = f2t(aR[p].y);
            ar[2] = f2t(aR[p].z); ar[3] = f2t(aR[p].w);
            uint32_t* br = &Bs[bk + p * 8][bn];
            br[0] = f2t(bR[p].x); br[1] = f2t(bR[p].y);
            br[2] = f2t(bR[p].z); br[3] = f2t(bR[p].w);
        }
        __syncthreads();
        if (k0 + 32 < K) {
            #pragma unroll
            for (int p = 0; p < 4; p++) {
                int r = m0 + am + p * 32;
                aR[p] = (r < M)
                    ? *(const float4*)(A + (size_t)r * K + k0 + 32 + ak) : f4zero();
                bR[p] = *(const float4*)(Bm + (size_t)(k0 + 32 + bk + p * 8) * N + n0 + bn);
            }
        }
        #pragma unroll
        for (int ks = 0; ks < 4; ks++) {
            int kb = ks * 8;
            uint32_t a0[4], a1[4], a2[4], a3[4];
            #pragma unroll
            for (int mi = 0; mi < 4; mi++) {
                int mr = wm + mi * 16 + g;
                a0[mi] = As[mr][kb + tg];
                a1[mi] = As[mr + 8][kb + tg];
                a2[mi] = As[mr][kb + tg + 4];
                a3[mi] = As[mr + 8][kb + tg + 4];
            }
            #pragma unroll
            for (int ni = 0; ni < 4; ni++) {
                uint32_t b0 = Bs[kb + tg][wn + ni * 8 + g];
                uint32_t b1 = Bs[kb + tg + 4][wn + ni * 8 + g];
                #pragma unroll
                for (int mi = 0; mi < 4; mi++)
                    mma_tf32(acc[mi][ni], a0[mi], a1[mi], a2[mi], a3[mi], b0, b1);
            }
        }
    }

    #pragma unroll
    for (int mi = 0; mi < 4; mi++) {
        #pragma unroll
        for (int half = 0; half < 2; half++) {
            int r = m0 + wm + mi * 16 + g + half * 8;
            if (r < M) {
                #pragma unroll
                for (int ni = 0; ni < 4; ni++) {
                    int c = n0 + wn + ni * 8 + tg * 2;
                    float v0 = acc[mi][ni][half * 2 + 0];
                    float v1 = acc[mi][ni][half * 2 + 1];
                    if (EPI >= 1) { v0 += bias[c]; v1 += bias[c + 1]; }
                    if (EPI == 2) {
                        v0 += res[(size_t)r * N + c];
                        v1 += res[(size_t)r * N + c + 1];
                    }
                    if (EPI == 3) { v0 = gelu_f(v0); v1 = gelu_f(v1); }
                    *(float2*)&C[(size_t)r * N + c] = make_float2(v0, v1);
                }
            }
        }
    }
}

// ---------------------------------------------------------------------------
// Scores: S[bh][i][j] = SCALE * Q[i,:] . K[j,:]   (128x128 tile, d=64)
// Qs/Ks stored [token][d] pad68 (direct copy; frag lane->bank bijective).
// grid (9, 9, 128), dynamic smem 2*128*68*4 = 69632 B.
// ---------------------------------------------------------------------------
__global__ void __launch_bounds__(256) score_mma_kernel(
    const float* __restrict__ qkv, float* __restrict__ S)
{
    extern __shared__ uint32_t smd[];
    uint32_t (*Qs)[68] = (uint32_t(*)[68])smd;
    uint32_t (*Ks)[68] = (uint32_t(*)[68])(smd + 128 * 68);

    int bh = blockIdx.z, b = bh >> 4, h = bh & 15;
    const float* Qp = qkv + (size_t)b * SEQ * (3 * EMB) + h * HD;
    const float* Kp = Qp + EMB;
    int i0 = blockIdx.y * 128, j0 = blockIdx.x * 128;
    int t = threadIdx.x;
    int w = t >> 5, lane = t & 31;
    int wm = (w >> 2) * 64, wn = (w & 3) * 32;
    int g = lane >> 2, tg = lane & 3;

    int lr = t >> 4, lc = (t & 15) << 2;   // 16 rows/pass x 16 float4, 8 passes
    #pragma unroll
    for (int p = 0; p < 8; p++) {
        int r = lr + p * 16;
        float4 q = (i0 + r < SEQ)
            ? *(const float4*)(Qp + (size_t)(i0 + r) * (3 * EMB) + lc) : f4zero();
        float4 kk = (j0 + r < SEQ)
            ? *(const float4*)(Kp + (size_t)(j0 + r) * (3 * EMB) + lc) : f4zero();
        uint32_t* qr = &Qs[r][lc];
        qr[0] = f2t(q.x); qr[1] = f2t(q.y); qr[2] = f2t(q.z); qr[3] = f2t(q.w);
        uint32_t* kr = &Ks[r][lc];
        kr[0] = f2t(kk.x); kr[1] = f2t(kk.y); kr[2] = f2t(kk.z); kr[3] = f2t(kk.w);
    }
    __syncthreads();

    float acc[4][4][4];
    #pragma unroll
    for (int i = 0; i < 4; i++)
        #pragma unroll
        for (int j = 0; j < 4; j++)
            #pragma unroll
            for (int q = 0; q < 4; q++) acc[i][j][q] = 0.f;

    #pragma unroll
    for (int ks = 0; ks < 8; ks++) {
        int kb = ks * 8;
        uint32_t a0[4], a1[4], a2[4], a3[4];
        #pragma unroll
        for (int mi = 0; mi < 4; mi++) {
            int mr = wm + mi * 16 + g;
            a0[mi] = Qs[mr][kb + tg];
            a1[mi] = Qs[mr + 8][kb + tg];
            a2[mi] = Qs[mr][kb + tg + 4];
            a3[mi] = Qs[mr + 8][kb + tg + 4];
        }
        #pragma unroll
        for (int ni = 0; ni < 4; ni++) {
            int nr = wn + ni * 8 + g;
            uint32_t b0 = Ks[nr][kb + tg];
            uint32_t b1 = Ks[nr][kb + tg + 4];
            #pragma unroll
            for (int mi = 0; mi < 4; mi++)
                mma_tf32(acc[mi][ni], a0[mi], a1[mi], a2[mi], a3[mi], b0, b1);
        }
    }

    float* Sp = S + (size_t)bh * SPAD * SPAD;
    #pragma unroll
    for (int mi = 0; mi < 4; mi++) {
        #pragma unroll
        for (int half = 0; half < 2; half++) {
            int r = i0 + wm + mi * 16 + g + half * 8;    // < 1152 always
            #pragma unroll
            for (int ni = 0; ni < 4; ni++) {
                int c = j0 + wn + ni * 8 + tg * 2;
                float v0 = acc[mi][ni][half * 2 + 0] * ATT_SCALE;
                float v1 = acc[mi][ni][half * 2 + 1] * ATT_SCALE;
                *(float2*)&Sp[(size_t)r * SPAD + c] = make_float2(v0, v1);
            }
        }
    }
}

// ---------------------------------------------------------------------------
// Masked softmax over key dim. One block (128 thr) per (row, bh).
// j in [SEQ, SPAD) stays 0 in scratch (score kernel wrote 0 there via zero-K).
// ---------------------------------------------------------------------------
__global__ void __launch_bounds__(128) softmax_kernel(
    float* __restrict__ S, const float* __restrict__ mask)
{
    int row = blockIdx.x;
    int bh  = blockIdx.y;
    int b = bh >> 4;
    float* Sp = S + ((size_t)bh * SPAD + row) * SPAD;
    const float* mrow = (row >= NPATCH)
        ? mask + ((size_t)b * NQ + (row - NPATCH)) * NPATCH : nullptr;
    int t = threadIdx.x;

    float v[9];
    float mx = -3.0e38f;
    #pragma unroll
    for (int i = 0; i < 9; i++) {
        int j = t + i * 128;
        float val = -3.0e38f;
        if (j < SEQ) {
            val = Sp[j];
            if (mrow && j < NPATCH && !(mrow[j] > 0.5f)) val = -1.0e9f;
        }
        v[i] = val;
        mx = fmaxf(mx, val);
    }

    __shared__ float redm[4];
    __shared__ float reds[4];
    #pragma unroll
    for (int o = 16; o > 0; o >>= 1)
        mx = fmaxf(mx, __shfl_xor_sync(0xffffffffu, mx, o));
    if ((t & 31) == 0) redm[t >> 5] = mx;
    __syncthreads();
    mx = fmaxf(fmaxf(redm[0], redm[1]), fmaxf(redm[2], redm[3]));

    float sum = 0.f;
    #pragma unroll
    for (int i = 0; i < 9; i++) {
        float e = __expf(v[i] - mx);
        v[i] = e;
        sum += e;
    }
    #pragma unroll
    for (int o = 16; o > 0; o >>= 1)
        sum += __shfl_xor_sync(0xffffffffu, sum, o);
    if ((t & 31) == 0) reds[t >> 5] = sum;
    __syncthreads();
    sum = reds[0] + reds[1] + reds[2] + reds[3];
    float inv = __fdividef(1.0f, sum);

    #pragma unroll
    for (int i = 0; i < 9; i++) {
        int j = t + i * 128;
        if (j < SEQ) Sp[j] = v[i] * inv;
    }
}

// ---------------------------------------------------------------------------
// AV: out[b,i,h*64+d] = sum_j attn[bh][i][j] * V[b,j,h,d]
// Block tile 128 x 64, j loop step 32 over SPAD. 8 warps (4x2), warp 32x32.
// attn j >= SEQ entries are exactly 0 -> no value guard needed on A.
// ---------------------------------------------------------------------------
__global__ void __launch_bounds__(256) av_mma_kernel(
    const float* __restrict__ qkv, const float* __restrict__ attn,
    float* __restrict__ outp)
{
    __shared__ uint32_t Aa[128][36];
    __shared__ uint32_t Vs[32][72];
    int bh = blockIdx.y, b = bh >> 4, h = bh & 15;
    const float* Vp = qkv + (size_t)b * SEQ * (3 * EMB) + 2 * EMB + h * HD;
    const float* Ap = attn + (size_t)bh * SPAD * SPAD;
    int i0 = blockIdx.x * 128;
    int t = threadIdx.x;
    int w = t >> 5, lane = t & 31;
    int wm = (w >> 1) * 32, wn = (w & 1) * 32;
    int g = lane >> 2, tg = lane & 3;

    int am = t >> 3, ak = (t & 7) << 2;    // attn: 32 rows/pass, 4 passes
    int vr = t >> 4, vc = (t & 15) << 2;   // V: 16 rows/pass, 2 passes

    float4 aR[4], vR[2];
    #pragma unroll
    for (int p = 0; p < 4; p++)
        aR[p] = *(const float4*)(Ap + (size_t)(i0 + am + p * 32) * SPAD + ak);
    #pragma unroll
    for (int p = 0; p < 2; p++) {
        int r = vr + p * 16;
        vR[p] = (r < SEQ)
            ? *(const float4*)(Vp + (size_t)r * (3 * EMB) + vc) : f4zero();
    }

    float acc[2][4][4];
    #pragma unroll
    for (int i = 0; i < 2; i++)
        #pragma unroll
        for (int j = 0; j < 4; j++)
            #pragma unroll
            for (int q = 0; q < 4; q++) acc[i][j][q] = 0.f;

    for (int j0 = 0; j0 < SPAD; j0 += 32) {
        __syncthreads();
        #pragma unroll
        for (int p = 0; p < 4; p++) {
            uint32_t* ar = &Aa[am + p * 32][ak];
            ar[0] = f2t(aR[p].x); ar[1] = f2t(aR[p].y);
            ar[2] = f2t(aR[p].z); ar[3] = f2t(aR[p].w);
        }
        #pragma unroll
        for (int p = 0; p < 2; p++) {
            uint32_t* vrow = &Vs[vr + p * 16][vc];
            vrow[0] = f2t(vR[p].x); vrow[1] = f2t(vR[p].y);
            vrow[2] = f2t(vR[p].z); vrow[3] = f2t(vR[p].w);
        }
        __syncthreads();
        if (j0 + 32 < SPAD) {
            #pragma unroll
            for (int p = 0; p < 4; p++)
                aR[p] = *(const float4*)(Ap + (size_t)(i0 + am + p * 32) * SPAD
                                         + j0 + 32 + ak);
            #pragma unroll
            for (int p = 0; p < 2; p++) {
                int r = j0 + 32 + vr + p * 16;
                vR[p] = (r < SEQ)
                    ? *(const float4*)(Vp + (size_t)r * (3 * EMB) + vc) : f4zero();
            }
        }
        #pragma unroll
        for (int ks = 0; ks < 4; ks++) {
            int kb = ks * 8;
            uint32_t a0[2], a1[2], a2[2], a3[2];
            #pragma unroll
            for (int mi = 0; mi < 2; mi++) {
                int mr = wm + mi * 16 + g;
                a0[mi] = Aa[mr][kb + tg];
                a1[mi] = Aa[mr + 8][kb + tg];
                a2[mi] = Aa[mr][kb + tg + 4];
                a3[mi] = Aa[mr + 8][kb + tg + 4];
            }
            #pragma unroll
            for (int ni = 0; ni < 4; ni++) {
                uint32_t b0 = Vs[kb + tg][wn + ni * 8 + g];
                uint32_t b1 = Vs[kb + tg + 4][wn + ni * 8 + g];
                #pragma unroll
                for (int mi = 0; mi < 2; mi++)
                    mma_tf32(acc[mi][ni], a0[mi], a1[mi], a2[mi], a3[mi], b0, b1);
            }
        }
    }

    #pragma unroll
    for (int mi = 0; mi < 2; mi++) {
        #pragma unroll
        for (int half = 0; half < 2; half++) {
            int r = i0 + wm + mi * 16 + g + half * 8;
            if (r < SEQ) {
                #pragma unroll
                for (int ni = 0; ni < 4; ni++) {
                    int c = h * HD + wn + ni * 8 + tg * 2;
                    float v0 = acc[mi][ni][half * 2 + 0];
                    float v1 = acc[mi][ni][half * 2 + 1];
                    *(float2*)&outp[((size_t)b * SEQ + r) * EMB + c]
                        = make_float2(v0, v1);
                }
            }
        }
    }
}

// ---------------------------------------------------------------------------
extern "C" void kernel_launch(void* const* d_in, const int* in_sizes, int n_in,
                              void* d_out, int out_size)
{
    (void)in_sizes; (void)n_in; (void)out_size;
    const float* x      = (const float*)d_in[0];
    const float* mask   = (const float*)d_in[1];
    const float* qkv_w  = (const float*)d_in[2];
    const float* proj_w = (const float*)d_in[3];
    const float* proj_b = (const float*)d_in[4];
    const float* ln1_g  = (const float*)d_in[5];
    const float* ln1_b  = (const float*)d_in[6];
    const float* ln2_g  = (const float*)d_in[7];
    const float* ln2_b  = (const float*)d_in[8];
    const float* fc1_w  = (const float*)d_in[9];
    const float* fc1_b  = (const float*)d_in[10];
    const float* fc2_w  = (const float*)d_in[11];
    const float* fc2_b  = (const float*)d_in[12];
    float* out = (float*)d_out;

    float* scratch = nullptr;
    cudaGetSymbolAddress((void**)&scratch, g_scratch);
    float* xn   = scratch + OFF_XN;
    float* qkv  = scratch + OFF_QKV;
    float* sc   = scratch + OFF_SC;
    float* att  = scratch + OFF_ATT;
    float* x1   = scratch + OFF_X1;
    float* h1   = scratch + OFF_H1;

    // Idempotent, deterministic on every call (no static guards allowed).
    cudaFuncSetAttribute(score_mma_kernel,
                         cudaFuncAttributeMaxDynamicSharedMemorySize,
                         2 * 128 * 68 * 4);

    const int MT = (NROWS + 127) / 128;  // 71

    // 1. LN1
    ln_kernel<<<NROWS, 256>>>(x, ln1_g, ln1_b, xn);
    // 2. QKV = xn @ qkv_w
    tgemm_kernel<0><<<dim3(3 * EMB / 128, MT), 256>>>(
        xn, qkv_w, qkv, NROWS, 3 * EMB, EMB, nullptr, nullptr);
    // 3. scores
    score_mma_kernel<<<dim3(SPAD / 128, SPAD / 128, BB * NH), 256,
                       2 * 128 * 68 * 4>>>(qkv, sc);
    // 4. masked softmax
    softmax_kernel<<<dim3(SEQ, BB * NH), 128>>>(sc, mask);
    // 5. att = attn @ V
    av_mma_kernel<<<dim3(SPAD / 128, BB * NH), 256>>>(qkv, sc, att);
    // 6. x1 = x + att @ proj_w + proj_b
    tgemm_kernel<2><<<dim3(EMB / 128, MT), 256>>>(
        att, proj_w, x1, NROWS, EMB, EMB, proj_b, x);
    // 7. LN2
    ln_kernel<<<NROWS, 256>>>(x1, ln2_g, ln2_b, xn);
    // 8. h1 = gelu(xn @ fc1_w + fc1_b)
    tgemm_kernel<3><<<dim3(MLPH / 128, MT), 256>>>(
        xn, fc1_w, h1, NROWS, MLPH, EMB, fc1_b, nullptr);
    // 9. out = x1 + h1 @ fc2_w + fc2_b
    tgemm_kernel<2><<<dim3(EMB / 128, MT), 256>>>(
        h1, fc2_w, out, NROWS, EMB, MLPH, fc2_b, x1);
}